// round 9
// baseline (speedup 1.0000x reference)
#include <cuda_runtime.h>
#include <cuda_bf16.h>

// ONE kernel: ticket-based compaction + producer-counter wait (no all-arrive
// grid barrier), packed f32x2 pair phase, slotted fp64 accumulation.
// n=1024, K=8 -> 8192 entries.
//   total = sum_{a in pos, b in neg} log(1 + exp(v_b - v_a)) / (P*N)
// Restructurings:
//   exp(q-p) = exp(q)*exp(-p)           (per-entry exps, compaction phase)
//   sum log(1+t) = (sum log2 prod(t/64) + corr) * ln2   (no renorm needed)
//   fma.rn.f32x2 / mul.rn.f32x2: one instruction covers 2 pairs.
// Pads: device globals zero-init; pad slots are NEVER written. Zero pad =>
// t' = 1/64 => log2 + correction contribution exactly 0.

#define CAP     16640
#define GRID    148
#define TPB     1024
#define WARPS   (TPB / 32)
#define NCHUNK  8          // compaction chunks (8 x 1024 = 8192 elements)
#define NSLOT   16         // fp64 accumulation slots

__device__ float  g_posExp[CAP];
__device__ float  g_negExp[CAP];
__device__ unsigned int g_PN;        // packed: P | (N << 16)
__device__ unsigned int g_ticket;    // compaction work tickets (reset per call)
__device__ unsigned int g_ready;     // completed chunks        (reset per call)
__device__ unsigned int g_done;      // finished blocks         (reset per call)
__device__ double g_accSlot[NSLOT];

typedef unsigned long long u64;

__device__ __forceinline__ u64 pk2(float lo, float hi) {
    u64 r; asm("mov.b64 %0, {%1, %2};" : "=l"(r) : "f"(lo), "f"(hi)); return r;
}
__device__ __forceinline__ void upk2(u64 v, float& lo, float& hi) {
    asm("mov.b64 {%0, %1}, %2;" : "=f"(lo), "=f"(hi) : "l"(v));
}
__device__ __forceinline__ u64 fma2(u64 a, u64 b, u64 c) {
    u64 d; asm("fma.rn.f32x2 %0, %1, %2, %3;" : "=l"(d) : "l"(a), "l"(b), "l"(c));
    return d;
}
__device__ __forceinline__ u64 mul2(u64 a, u64 b) {
    u64 d; asm("mul.rn.f32x2 %0, %1, %2;" : "=l"(d) : "l"(a), "l"(b));
    return d;
}

// Product over one negative float4 of t' = (q*F + 1)/64, for 2 packed positives.
__device__ __forceinline__ u64 tprod4(u64 qx, u64 qy, u64 qz, u64 qw,
                                      u64 Fs, u64 S2) {
    u64 t0 = fma2(qx, Fs, S2);
    u64 t1 = fma2(qy, Fs, S2);
    u64 t2 = fma2(qz, Fs, S2);
    u64 t3 = fma2(qw, Fs, S2);
    return mul2(mul2(t0, t1), mul2(t2, t3));
}

__global__ void __launch_bounds__(TPB, 1)
rul_fused_kernel(const float* __restrict__ pred,
                 const int* __restrict__ label,
                 int total,
                 float* __restrict__ out) {
    const int tid = blockIdx.x * blockDim.x + threadIdx.x;
    const int nthreads = GRID * TPB;

    __shared__ unsigned int sCnt[WARPS];
    __shared__ unsigned int sBase[WARPS];
    __shared__ unsigned int sBlockBase;
    __shared__ unsigned int sChunk;
    __shared__ unsigned int sPN;
    __shared__ float        sRed[WARPS];

    const unsigned lane = threadIdx.x & 31u;
    const unsigned warp = threadIdx.x >> 5;

    // -------- Phase 1: ticket-claimed compaction chunks ----------------------
    // First blocks to launch grab all NCHUNK chunks; late blocks fall through.
    for (;;) {
        if (threadIdx.x == 0) sChunk = atomicAdd(&g_ticket, 1u);
        __syncthreads();
        unsigned chunk = sChunk;
        if (chunk >= NCHUNK) break;

        int i = (int)chunk * TPB + threadIdx.x;
        float v = 0.0f;
        int yy = -1;
        if (i < total) { v = pred[i]; yy = label[i]; }
        bool isPos = (yy == 1);
        bool isNeg = (yy == 0);

        unsigned mp = __ballot_sync(0xFFFFFFFFu, isPos);
        unsigned mn = __ballot_sync(0xFFFFFFFFu, isNeg);
        unsigned ltmask = (1u << lane) - 1u;

        if (lane == 0)
            sCnt[warp] = (unsigned)__popc(mp) | ((unsigned)__popc(mn) << 16);
        __syncthreads();

        if (threadIdx.x == 0) {
            unsigned run = 0;
#pragma unroll
            for (int w = 0; w < WARPS; ++w) { sBase[w] = run; run += sCnt[w]; }
            sBlockBase = atomicAdd(&g_PN, run);   // packed: fields < 2^16
        }
        __syncthreads();

        unsigned base = sBlockBase + sBase[warp];
        int basep = (int)(base & 0xFFFFu);
        int basen = (int)(base >> 16);
        if (isPos) g_posExp[basep + __popc(mp & ltmask)] = expf(-v);
        if (isNeg) g_negExp[basen + __popc(mn & ltmask)] = expf(v);

        __syncthreads();
        if (threadIdx.x == 0) {
            __threadfence();
            atomicAdd(&g_ready, 1u);
        }
    }

    // -------- Wait only for the 8 producer chunks (not all CTAs) -------------
    if (threadIdx.x == 0) {
        while (*(volatile unsigned int*)&g_ready < NCHUNK) { /* spin */ }
        __threadfence();
        sPN = *(volatile unsigned int*)&g_PN;
    }
    __syncthreads();

    // -------- Phase 2: packed all-pairs product chains -----------------------
    const unsigned pn = sPN;
    const int P = (int)(pn & 0xFFFFu);
    const int N = (int)(pn >> 16);
    int G8 = (P + 7) >> 3;
    if (G8 < 1) G8 = 1;
    const int nf4 = (N + 3) >> 2;
    int nseg = nthreads / G8;
    if (nseg < 1) nseg = 1;
    const int nchunks = (nf4 + 4 * nseg - 1) / (4 * nseg);
    const int segLen  = nchunks * 4;
    const int units   = G8 * nseg;

    const float4* __restrict__ negf4 = reinterpret_cast<const float4*>(g_negExp);
    const float4* __restrict__ posf4 = reinterpret_cast<const float4*>(g_posExp);

    const u64 S2 = pk2(0.015625f, 0.015625f);   // 1/64

    float threadSum = 0.0f;
    if (tid < units) {
        int seg = tid / G8;
        int pg  = tid - seg * G8;

        float4 Fa = posf4[2 * pg];
        float4 Fb = posf4[2 * pg + 1];
        u64 Fs0 = mul2(pk2(Fa.x, Fa.y), S2);
        u64 Fs1 = mul2(pk2(Fa.z, Fa.w), S2);
        u64 Fs2 = mul2(pk2(Fb.x, Fb.y), S2);
        u64 Fs3 = mul2(pk2(Fb.z, Fb.w), S2);

        float lg = 0.0f;
        int j0 = seg * segLen;
        for (int c = 0; c < nchunks; ++c) {
            const float4* qp = negf4 + j0 + c * 4;
            u64 m0 = 0, m1 = 0, m2 = 0, m3 = 0;
#pragma unroll
            for (int k = 0; k < 4; ++k) {
                float4 q = qp[k];
                u64 qx = pk2(q.x, q.x), qy = pk2(q.y, q.y);
                u64 qz = pk2(q.z, q.z), qw = pk2(q.w, q.w);
                u64 p0 = tprod4(qx, qy, qz, qw, Fs0, S2);
                u64 p1 = tprod4(qx, qy, qz, qw, Fs1, S2);
                u64 p2 = tprod4(qx, qy, qz, qw, Fs2, S2);
                u64 p3 = tprod4(qx, qy, qz, qw, Fs3, S2);
                if (k == 0) { m0 = p0; m1 = p1; m2 = p2; m3 = p3; }
                else {
                    m0 = mul2(m0, p0); m1 = mul2(m1, p1);
                    m2 = mul2(m2, p2); m3 = mul2(m3, p3);
                }
            }
            float a, b;
            upk2(m0, a, b); lg += __log2f(a) + __log2f(b);
            upk2(m1, a, b); lg += __log2f(a) + __log2f(b);
            upk2(m2, a, b); lg += __log2f(a) + __log2f(b);
            upk2(m3, a, b); lg += __log2f(a) + __log2f(b);
        }
        // +16*log2(64)=96 per scalar chain-chunk, 8 chains. Pads cancel exactly.
        threadSum = (lg + (float)(768 * nchunks)) * 0.6931471805599453f;
    }

    // -------- Block reduction ------------------------------------------------
#pragma unroll
    for (int off = 16; off > 0; off >>= 1)
        threadSum += __shfl_down_sync(0xFFFFFFFFu, threadSum, off);
    if (lane == 0) sRed[warp] = threadSum;
    __syncthreads();
    if (warp == 0) {
        float s = (lane < WARPS) ? sRed[lane] : 0.0f;
#pragma unroll
        for (int off = 16; off > 0; off >>= 1)
            s += __shfl_down_sync(0xFFFFFFFFu, s, off);

        // -------- Phase 3: slotted accumulate + last-block finalize ----------
        if (lane == 0) {
            atomicAdd(&g_accSlot[blockIdx.x & (NSLOT - 1)], (double)s);
            __threadfence();
            unsigned int d = atomicAdd(&g_done, 1u);
            if (d == GRID - 1) {
                __threadfence();
                double acc = 0.0;
#pragma unroll
                for (int k = 0; k < NSLOT; ++k) {
                    acc += *(volatile double*)&g_accSlot[k];
                    g_accSlot[k] = 0.0;
                }
                double denom = (double)P * (double)N;
                out[0] = (float)(acc / denom);
                // Reset all per-call state (replays are stream-serialized, and
                // every other block has already passed all reads of these).
                g_PN = 0u;
                g_ticket = 0u;
                g_ready = 0u;
                g_done = 0u;
            }
        }
    }
}

// ---------------------------------------------------------------------------
extern "C" void kernel_launch(void* const* d_in, const int* in_sizes, int n_in,
                              void* d_out, int out_size) {
    const float* pred  = (const float*)d_in[0];
    const int*   label = (const int*)d_in[1];
    int total = in_sizes[0];   // n*K = 8192

    rul_fused_kernel<<<GRID, TPB>>>(pred, label, total, (float*)d_out);
}

// round 10
// speedup vs baseline: 1.1240x; 1.1240x over previous
#include <cuda_runtime.h>
#include <cuda_bf16.h>

// ONE kernel, ZERO inter-block sync. n=1024, K=8 -> 8192 entries.
//   total = sum_{a in pos, b in neg} log(1 + exp(v_b - v_a)) / (P*N)
//
// Tile decomposition: entries split into RNG=12 ranges (683 each). Block
// b=(i,j) locally compacts positives of range i and negatives of range j
// into SMEM (ballot + smem atomic; order irrelevant), then computes its
// pos-tile x neg-tile pairs from SMEM. Union over 144 blocks covers every
// cross pair exactly once -> no grid barrier, no multi-kernel graph.
//
// Pair math (validated rel_err ~2e-7):
//   exp(q-p) = exp(q)*exp(-p);  sum log(1+t) = (sum log2 prod(t/64)+corr)*ln2
//   fma.rn.f32x2 / mul.rn.f32x2 packed: 1 instruction covers 2 pairs.
// Zero-padded SMEM slots give t' = 1/64 whose log2 exactly cancels the +6
// per-pair correction.

#define RNG    12
#define RSZ    683            // 12*683 = 8196 >= 8192
#define GRID   (RNG * RNG)    // 144
#define TPB    1024
#define WARPS  (TPB / 32)
#define LCAP   704            // smem list capacity (>= 688, /16 aligned)
#define NSLOT  16

__device__ unsigned int g_P;        // global positive count   (reset per call)
__device__ unsigned int g_N;        // global negative count   (reset per call)
__device__ unsigned int g_done;     // finished blocks         (reset per call)
__device__ double g_accSlot[NSLOT];

typedef unsigned long long u64;

__device__ __forceinline__ u64 pk2(float lo, float hi) {
    u64 r; asm("mov.b64 %0, {%1, %2};" : "=l"(r) : "f"(lo), "f"(hi)); return r;
}
__device__ __forceinline__ void upk2(u64 v, float& lo, float& hi) {
    asm("mov.b64 {%0, %1}, %2;" : "=f"(lo), "=f"(hi) : "l"(v));
}
__device__ __forceinline__ u64 fma2(u64 a, u64 b, u64 c) {
    u64 d; asm("fma.rn.f32x2 %0, %1, %2, %3;" : "=l"(d) : "l"(a), "l"(b), "l"(c));
    return d;
}
__device__ __forceinline__ u64 mul2(u64 a, u64 b) {
    u64 d; asm("mul.rn.f32x2 %0, %1, %2;" : "=l"(d) : "l"(a), "l"(b));
    return d;
}

// Product over one negative float4 of t' = (q*F + 1)/64, for 2 packed positives.
__device__ __forceinline__ u64 tprod4(u64 qx, u64 qy, u64 qz, u64 qw,
                                      u64 Fs, u64 S2) {
    u64 t0 = fma2(qx, Fs, S2);
    u64 t1 = fma2(qy, Fs, S2);
    u64 t2 = fma2(qz, Fs, S2);
    u64 t3 = fma2(qw, Fs, S2);
    return mul2(mul2(t0, t1), mul2(t2, t3));
}

__global__ void __launch_bounds__(TPB, 1)
rul_tile_kernel(const float* __restrict__ pred,
                const int* __restrict__ label,
                int total,
                float* __restrict__ out) {
    __shared__ __align__(16) float sPos[LCAP];   // exp(-v) list, zero padded
    __shared__ __align__(16) float sNeg[LCAP];   // exp(+v) list, zero padded
    __shared__ unsigned int sCntP, sCntN;
    __shared__ float sRed[WARPS];

    const unsigned lane = threadIdx.x & 31u;
    const unsigned warp = threadIdx.x >> 5;
    const unsigned ltmask = (1u << lane) - 1u;
    const int pi = blockIdx.x / RNG;     // positive range index
    const int nj = blockIdx.x % RNG;     // negative range index

    // ---- zero lists + counters ---------------------------------------------
    if (threadIdx.x < LCAP) { sPos[threadIdx.x] = 0.0f; sNeg[threadIdx.x] = 0.0f; }
    if (threadIdx.x == 0) { sCntP = 0u; sCntN = 0u; }
    __syncthreads();

    // ---- local compaction: positives from range pi --------------------------
    {
        int idx = (int)threadIdx.x;                 // RSZ <= TPB: single pass
        int i = pi * RSZ + idx;
        bool inR = (idx < RSZ) && (i < total);
        float v = 0.0f; int yy = -1;
        if (inR) { v = pred[i]; yy = label[i]; }
        bool isPos = inR && (yy == 1);
        unsigned mp = __ballot_sync(0xFFFFFFFFu, isPos);
        unsigned wbase = 0;
        if (lane == 0 && mp) wbase = atomicAdd(&sCntP, (unsigned)__popc(mp));
        wbase = __shfl_sync(0xFFFFFFFFu, wbase, 0);
        if (isPos) sPos[wbase + __popc(mp & ltmask)] = expf(-v);
    }
    // ---- local compaction: negatives from range nj --------------------------
    {
        int idx = (int)threadIdx.x;
        int i = nj * RSZ + idx;
        bool inR = (idx < RSZ) && (i < total);
        float v = 0.0f; int yy = -1;
        if (inR) { v = pred[i]; yy = label[i]; }
        bool isNeg = inR && (yy == 0);
        unsigned mn = __ballot_sync(0xFFFFFFFFu, isNeg);
        unsigned wbase = 0;
        if (lane == 0 && mn) wbase = atomicAdd(&sCntN, (unsigned)__popc(mn));
        wbase = __shfl_sync(0xFFFFFFFFu, wbase, 0);
        if (isNeg) sNeg[wbase + __popc(mn & ltmask)] = expf(v);
    }
    __syncthreads();

    const int cntP = (int)sCntP;
    const int cntN = (int)sCntN;

    // Contribute local counts to global P,N (each range counted once).
    if (threadIdx.x == 0) {
        if (nj == 0 && cntP) atomicAdd(&g_P, (unsigned)cntP);
        if (pi == 0 && cntN) atomicAdd(&g_N, (unsigned)cntN);
    }

    // ---- pair phase from SMEM ------------------------------------------------
    int G8 = (cntP + 7) >> 3;                 // pos groups of 8
    int nChunk = (cntN + 15) >> 4;            // neg chunks of 16
    const int units = G8 * nChunk;            // ~950 <= TPB typically

    const float4* __restrict__ posf4 = reinterpret_cast<const float4*>(sPos);
    const float4* __restrict__ negf4 = reinterpret_cast<const float4*>(sNeg);
    const u64 S2 = pk2(0.015625f, 0.015625f); // 1/64

    float lgSum = 0.0f;
    int   nUnits = 0;
    for (int u = (int)threadIdx.x; u < units; u += TPB) {
        int chunk = u / G8;                   // consecutive threads share chunk
        int pg    = u - chunk * G8;

        float4 Fa = posf4[2 * pg];
        float4 Fb = posf4[2 * pg + 1];
        u64 Fs0 = mul2(pk2(Fa.x, Fa.y), S2);
        u64 Fs1 = mul2(pk2(Fa.z, Fa.w), S2);
        u64 Fs2 = mul2(pk2(Fb.x, Fb.y), S2);
        u64 Fs3 = mul2(pk2(Fb.z, Fb.w), S2);

        const float4* qp = negf4 + chunk * 4;
        u64 m0 = 0, m1 = 0, m2 = 0, m3 = 0;
#pragma unroll
        for (int k = 0; k < 4; ++k) {
            float4 q = qp[k];
            u64 qx = pk2(q.x, q.x), qy = pk2(q.y, q.y);
            u64 qz = pk2(q.z, q.z), qw = pk2(q.w, q.w);
            u64 p0 = tprod4(qx, qy, qz, qw, Fs0, S2);
            u64 p1 = tprod4(qx, qy, qz, qw, Fs1, S2);
            u64 p2 = tprod4(qx, qy, qz, qw, Fs2, S2);
            u64 p3 = tprod4(qx, qy, qz, qw, Fs3, S2);
            if (k == 0) { m0 = p0; m1 = p1; m2 = p2; m3 = p3; }
            else {
                m0 = mul2(m0, p0); m1 = mul2(m1, p1);
                m2 = mul2(m2, p2); m3 = mul2(m3, p3);
            }
        }
        float a, b;
        upk2(m0, a, b); lgSum += __log2f(a) + __log2f(b);
        upk2(m1, a, b); lgSum += __log2f(a) + __log2f(b);
        upk2(m2, a, b); lgSum += __log2f(a) + __log2f(b);
        upk2(m3, a, b); lgSum += __log2f(a) + __log2f(b);
        ++nUnits;
    }
    // +16*log2(64) = 96 per scalar chain (8 chains/unit); pads cancel exactly.
    float threadSum = (lgSum + 768.0f * (float)nUnits) * 0.6931471805599453f;

    // ---- block reduction ------------------------------------------------------
#pragma unroll
    for (int off = 16; off > 0; off >>= 1)
        threadSum += __shfl_down_sync(0xFFFFFFFFu, threadSum, off);
    if (lane == 0) sRed[warp] = threadSum;
    __syncthreads();
    if (warp == 0) {
        float s = (lane < WARPS) ? sRed[lane] : 0.0f;
#pragma unroll
        for (int off = 16; off > 0; off >>= 1)
            s += __shfl_down_sync(0xFFFFFFFFu, s, off);

        // ---- slotted accumulate + last-block finalize --------------------------
        if (lane == 0) {
            atomicAdd(&g_accSlot[blockIdx.x & (NSLOT - 1)], (double)s);
            __threadfence();
            unsigned int d = atomicAdd(&g_done, 1u);
            if (d == GRID - 1) {
                __threadfence();
                double acc = 0.0;
#pragma unroll
                for (int k = 0; k < NSLOT; ++k) {
                    acc += *(volatile double*)&g_accSlot[k];
                    g_accSlot[k] = 0.0;
                }
                double P = (double)*(volatile unsigned int*)&g_P;
                double N = (double)*(volatile unsigned int*)&g_N;
                out[0] = (float)(acc / (P * N));
                g_P = 0u;
                g_N = 0u;
                g_done = 0u;
            }
        }
    }
}

// ---------------------------------------------------------------------------
extern "C" void kernel_launch(void* const* d_in, const int* in_sizes, int n_in,
                              void* d_out, int out_size) {
    const float* pred  = (const float*)d_in[0];
    const int*   label = (const int*)d_in[1];
    int total = in_sizes[0];   // n*K = 8192

    rul_tile_kernel<<<GRID, TPB>>>(pred, label, total, (float*)d_out);
}

// round 11
// speedup vs baseline: 1.1895x; 1.0583x over previous
#include <cuda_runtime.h>
#include <cuda_bf16.h>

// ONE kernel, ZERO inter-block sync. n=1024, K=8 -> 8192 entries.
//   total = sum_{a in pos, b in neg} log(1 + exp(v_b - v_a)) / (P*N)
//
// Tile decomposition: entries split into RNG=17 ranges (482 each). Block
// b=(i,j) locally compacts positives of range i and negatives of range j
// into SMEM (ballot + smem atomic; order irrelevant), then computes its
// pos-tile x neg-tile pairs from SMEM. Union over 289 blocks covers every
// cross pair exactly once -> no grid barrier, no multi-kernel graph.
// 2 CTAs/SM co-resident: one block's FMA phase hides the other's load phase.
//
// Pair math (validated rel_err ~1e-7):
//   exp(q-p) = exp(q)*exp(-p);  sum log(1+t) = (sum log2 prod(t/64)+corr)*ln2
//   fma.rn.f32x2 / mul.rn.f32x2 packed: 1 instruction covers 2 pairs.
// Zero-padded SMEM slots give t' = 1/64 whose log2 exactly cancels the +6
// per-pair correction.

#define RNG    17
#define RSZ    482            // 17*482 = 8194 >= 8192
#define GRID   (RNG * RNG)    // 289
#define TPB    512
#define WARPS  (TPB / 32)
#define LCAP   496            // smem list capacity (>= 482+pad, /16 aligned)
#define NSLOT  16

__device__ unsigned int g_P;        // global positive count   (reset per call)
__device__ unsigned int g_N;        // global negative count   (reset per call)
__device__ unsigned int g_done;     // finished blocks         (reset per call)
__device__ double g_accSlot[NSLOT];

typedef unsigned long long u64;

__device__ __forceinline__ u64 pk2(float lo, float hi) {
    u64 r; asm("mov.b64 %0, {%1, %2};" : "=l"(r) : "f"(lo), "f"(hi)); return r;
}
__device__ __forceinline__ void upk2(u64 v, float& lo, float& hi) {
    asm("mov.b64 {%0, %1}, %2;" : "=f"(lo), "=f"(hi) : "l"(v));
}
__device__ __forceinline__ u64 fma2(u64 a, u64 b, u64 c) {
    u64 d; asm("fma.rn.f32x2 %0, %1, %2, %3;" : "=l"(d) : "l"(a), "l"(b), "l"(c));
    return d;
}
__device__ __forceinline__ u64 mul2(u64 a, u64 b) {
    u64 d; asm("mul.rn.f32x2 %0, %1, %2;" : "=l"(d) : "l"(a), "l"(b));
    return d;
}

// Product over one negative float4 of t' = (q*F + 1)/64, for 2 packed positives.
__device__ __forceinline__ u64 tprod4(u64 qx, u64 qy, u64 qz, u64 qw,
                                      u64 Fs, u64 S2) {
    u64 t0 = fma2(qx, Fs, S2);
    u64 t1 = fma2(qy, Fs, S2);
    u64 t2 = fma2(qz, Fs, S2);
    u64 t3 = fma2(qw, Fs, S2);
    return mul2(mul2(t0, t1), mul2(t2, t3));
}

__global__ void __launch_bounds__(TPB, 2)
rul_tile_kernel(const float* __restrict__ pred,
                const int* __restrict__ label,
                int total,
                float* __restrict__ out) {
    __shared__ __align__(16) float sPos[LCAP];   // exp(-v) list, zero padded
    __shared__ __align__(16) float sNeg[LCAP];   // exp(+v) list, zero padded
    __shared__ unsigned int sCntP, sCntN;
    __shared__ float sRed[WARPS];

    const unsigned lane = threadIdx.x & 31u;
    const unsigned warp = threadIdx.x >> 5;
    const unsigned ltmask = (1u << lane) - 1u;
    const int pi = blockIdx.x / RNG;     // positive range index
    const int nj = blockIdx.x % RNG;     // negative range index

    // ---- zero lists + counters ---------------------------------------------
    if (threadIdx.x < LCAP) { sPos[threadIdx.x] = 0.0f; sNeg[threadIdx.x] = 0.0f; }
    if (threadIdx.x == 0) { sCntP = 0u; sCntN = 0u; }
    __syncthreads();

    // ---- local compaction (RSZ <= TPB: single pass each) --------------------
    {
        int idx = (int)threadIdx.x;
        int ip = pi * RSZ + idx;
        int in = nj * RSZ + idx;
        bool inRp = (idx < RSZ) && (ip < total);
        bool inRn = (idx < RSZ) && (in < total);
        float vp = 0.0f, vn = 0.0f;
        int yp = -1, yn = -1;
        if (inRp) { vp = pred[ip]; yp = label[ip]; }
        if (inRn) { vn = pred[in]; yn = label[in]; }
        bool isPos = inRp && (yp == 1);
        bool isNeg = inRn && (yn == 0);

        unsigned mp = __ballot_sync(0xFFFFFFFFu, isPos);
        unsigned mn = __ballot_sync(0xFFFFFFFFu, isNeg);
        unsigned bp = 0, bn = 0;
        if (lane == 0) {
            if (mp) bp = atomicAdd(&sCntP, (unsigned)__popc(mp));
            if (mn) bn = atomicAdd(&sCntN, (unsigned)__popc(mn));
        }
        bp = __shfl_sync(0xFFFFFFFFu, bp, 0);
        bn = __shfl_sync(0xFFFFFFFFu, bn, 0);
        if (isPos) sPos[bp + __popc(mp & ltmask)] = __expf(-vp);
        if (isNeg) sNeg[bn + __popc(mn & ltmask)] = __expf(vn);
    }
    __syncthreads();

    const int cntP = (int)sCntP;
    const int cntN = (int)sCntN;

    // Contribute local counts to global P,N (each range counted once).
    if (threadIdx.x == 0) {
        if (nj == 0 && cntP) atomicAdd(&g_P, (unsigned)cntP);
        if (pi == 0 && cntN) atomicAdd(&g_N, (unsigned)cntN);
    }

    // ---- pair phase from SMEM ------------------------------------------------
    int G8 = (cntP + 7) >> 3;                 // pos groups of 8
    int nChunk = (cntN + 15) >> 4;            // neg chunks of 16
    const int units = G8 * nChunk;            // ~496 <= TPB typically

    const float4* __restrict__ posf4 = reinterpret_cast<const float4*>(sPos);
    const float4* __restrict__ negf4 = reinterpret_cast<const float4*>(sNeg);
    const u64 S2 = pk2(0.015625f, 0.015625f); // 1/64

    float lgSum = 0.0f;
    int   nUnits = 0;
    for (int u = (int)threadIdx.x; u < units; u += TPB) {
        int chunk = u / G8;                   // consecutive threads share chunk
        int pg    = u - chunk * G8;

        float4 Fa = posf4[2 * pg];
        float4 Fb = posf4[2 * pg + 1];
        u64 Fs0 = mul2(pk2(Fa.x, Fa.y), S2);
        u64 Fs1 = mul2(pk2(Fa.z, Fa.w), S2);
        u64 Fs2 = mul2(pk2(Fb.x, Fb.y), S2);
        u64 Fs3 = mul2(pk2(Fb.z, Fb.w), S2);

        const float4* qp = negf4 + chunk * 4;
        u64 m0 = 0, m1 = 0, m2 = 0, m3 = 0;
#pragma unroll
        for (int k = 0; k < 4; ++k) {
            float4 q = qp[k];
            u64 qx = pk2(q.x, q.x), qy = pk2(q.y, q.y);
            u64 qz = pk2(q.z, q.z), qw = pk2(q.w, q.w);
            u64 p0 = tprod4(qx, qy, qz, qw, Fs0, S2);
            u64 p1 = tprod4(qx, qy, qz, qw, Fs1, S2);
            u64 p2 = tprod4(qx, qy, qz, qw, Fs2, S2);
            u64 p3 = tprod4(qx, qy, qz, qw, Fs3, S2);
            if (k == 0) { m0 = p0; m1 = p1; m2 = p2; m3 = p3; }
            else {
                m0 = mul2(m0, p0); m1 = mul2(m1, p1);
                m2 = mul2(m2, p2); m3 = mul2(m3, p3);
            }
        }
        float a, b;
        upk2(m0, a, b); lgSum += __log2f(a) + __log2f(b);
        upk2(m1, a, b); lgSum += __log2f(a) + __log2f(b);
        upk2(m2, a, b); lgSum += __log2f(a) + __log2f(b);
        upk2(m3, a, b); lgSum += __log2f(a) + __log2f(b);
        ++nUnits;
    }
    // +16*log2(64) = 96 per scalar chain (8 chains/unit); pads cancel exactly.
    float threadSum = (lgSum + 768.0f * (float)nUnits) * 0.6931471805599453f;

    // ---- block reduction ------------------------------------------------------
#pragma unroll
    for (int off = 16; off > 0; off >>= 1)
        threadSum += __shfl_down_sync(0xFFFFFFFFu, threadSum, off);
    if (lane == 0) sRed[warp] = threadSum;
    __syncthreads();
    if (warp == 0) {
        float s = (lane < WARPS) ? sRed[lane] : 0.0f;
#pragma unroll
        for (int off = 16; off > 0; off >>= 1)
            s += __shfl_down_sync(0xFFFFFFFFu, s, off);

        // ---- slotted accumulate + last-block finalize --------------------------
        if (lane == 0) {
            atomicAdd(&g_accSlot[blockIdx.x & (NSLOT - 1)], (double)s);
            __threadfence();
            unsigned int d = atomicAdd(&g_done, 1u);
            if (d == GRID - 1) {
                __threadfence();
                double acc = 0.0;
#pragma unroll
                for (int k = 0; k < NSLOT; ++k) {
                    acc += *(volatile double*)&g_accSlot[k];
                    g_accSlot[k] = 0.0;
                }
                double P = (double)*(volatile unsigned int*)&g_P;
                double N = (double)*(volatile unsigned int*)&g_N;
                out[0] = (float)(acc / (P * N));
                g_P = 0u;
                g_N = 0u;
                g_done = 0u;
            }
        }
    }
}

// ---------------------------------------------------------------------------
extern "C" void kernel_launch(void* const* d_in, const int* in_sizes, int n_in,
                              void* d_out, int out_size) {
    const float* pred  = (const float*)d_in[0];
    const int*   label = (const int*)d_in[1];
    int total = in_sizes[0];   // n*K = 8192

    rul_tile_kernel<<<GRID, TPB>>>(pred, label, total, (float*)d_out);
}

// round 12
// speedup vs baseline: 1.2143x; 1.0208x over previous
#include <cuda_runtime.h>
#include <cuda_bf16.h>

// ONE kernel, ZERO inter-block sync. n=1024, K=8 -> 8192 entries.
//   total = sum_{a in pos, b in neg} log(1 + exp(v_b - v_a)) / (P*N)
//
// Tile decomposition: entries split into RNG=24 ranges (342 each). Block
// b=(i,j) locally compacts positives of range i and negatives of range j
// into SMEM (ballot + smem atomic), then computes its pos-tile x neg-tile
// pairs from SMEM. Union over 576 blocks covers every cross pair exactly
// once -> no grid barrier, no multi-kernel graph.
// 4 CTAs/SM co-resident (256 thr x 64 regs x 4 = full RF): serial per-block
// critical paths overlap 4-way per SM.
//
// Pair math (validated rel_err ~1e-7):
//   exp(q-p) = exp(q)*exp(-p);  sum log(1+t) = (sum log2 prod(t/64)+corr)*ln2
//   fma.rn.f32x2 / mul.rn.f32x2 packed: 1 instruction covers 2 pairs.
// Zero-padded SMEM slots give t' = 1/64 whose log2 exactly cancels the +6
// per-pair correction.

#define RNG    24
#define RSZ    342            // 24*342 = 8208 >= 8192
#define GRID   (RNG * RNG)    // 576
#define TPB    256
#define WARPS  (TPB / 32)
#define LCAP   352            // smem list capacity (>= 344, /16 aligned)
#define NSLOT  16

__device__ unsigned int g_P;        // global positive count   (reset per call)
__device__ unsigned int g_N;        // global negative count   (reset per call)
__device__ unsigned int g_done;     // finished blocks         (reset per call)
__device__ double g_accSlot[NSLOT];

typedef unsigned long long u64;

__device__ __forceinline__ u64 pk2(float lo, float hi) {
    u64 r; asm("mov.b64 %0, {%1, %2};" : "=l"(r) : "f"(lo), "f"(hi)); return r;
}
__device__ __forceinline__ void upk2(u64 v, float& lo, float& hi) {
    asm("mov.b64 {%0, %1}, %2;" : "=f"(lo), "=f"(hi) : "l"(v));
}
__device__ __forceinline__ u64 fma2(u64 a, u64 b, u64 c) {
    u64 d; asm("fma.rn.f32x2 %0, %1, %2, %3;" : "=l"(d) : "l"(a), "l"(b), "l"(c));
    return d;
}
__device__ __forceinline__ u64 mul2(u64 a, u64 b) {
    u64 d; asm("mul.rn.f32x2 %0, %1, %2;" : "=l"(d) : "l"(a), "l"(b));
    return d;
}

// Product over one negative float4 of t' = (q*F + 1)/64, for 2 packed positives.
__device__ __forceinline__ u64 tprod4(u64 qx, u64 qy, u64 qz, u64 qw,
                                      u64 Fs, u64 S2) {
    u64 t0 = fma2(qx, Fs, S2);
    u64 t1 = fma2(qy, Fs, S2);
    u64 t2 = fma2(qz, Fs, S2);
    u64 t3 = fma2(qw, Fs, S2);
    return mul2(mul2(t0, t1), mul2(t2, t3));
}

__global__ void __launch_bounds__(TPB, 4)
rul_tile_kernel(const float* __restrict__ pred,
                const int* __restrict__ label,
                int total,
                float* __restrict__ out) {
    __shared__ __align__(16) float sPos[LCAP];   // exp(-v) list, zero padded
    __shared__ __align__(16) float sNeg[LCAP];   // exp(+v) list, zero padded
    __shared__ unsigned int sCntP, sCntN;
    __shared__ float sRed[WARPS];

    const unsigned lane = threadIdx.x & 31u;
    const unsigned warp = threadIdx.x >> 5;
    const unsigned ltmask = (1u << lane) - 1u;
    const int pi = blockIdx.x / RNG;     // positive range index
    const int nj = blockIdx.x % RNG;     // negative range index

    // ---- zero lists + counters ---------------------------------------------
    for (int k = (int)threadIdx.x; k < LCAP; k += TPB) {
        sPos[k] = 0.0f; sNeg[k] = 0.0f;
    }
    if (threadIdx.x == 0) { sCntP = 0u; sCntN = 0u; }
    __syncthreads();

    // ---- local compaction (RSZ > TPB: strided passes, all threads iterate) --
    for (int base = 0; base < RSZ; base += TPB) {
        int idx = base + (int)threadIdx.x;
        int ip = pi * RSZ + idx;
        int in = nj * RSZ + idx;
        bool inRp = (idx < RSZ) && (ip < total);
        bool inRn = (idx < RSZ) && (in < total);
        float vp = 0.0f, vn = 0.0f;
        int yp = -1, yn = -1;
        if (inRp) { vp = pred[ip]; yp = label[ip]; }
        if (inRn) { vn = pred[in]; yn = label[in]; }
        bool isPos = inRp && (yp == 1);
        bool isNeg = inRn && (yn == 0);

        unsigned mp = __ballot_sync(0xFFFFFFFFu, isPos);
        unsigned mn = __ballot_sync(0xFFFFFFFFu, isNeg);
        unsigned bp = 0, bn = 0;
        if (lane == 0) {
            if (mp) bp = atomicAdd(&sCntP, (unsigned)__popc(mp));
            if (mn) bn = atomicAdd(&sCntN, (unsigned)__popc(mn));
        }
        bp = __shfl_sync(0xFFFFFFFFu, bp, 0);
        bn = __shfl_sync(0xFFFFFFFFu, bn, 0);
        if (isPos) sPos[bp + __popc(mp & ltmask)] = __expf(-vp);
        if (isNeg) sNeg[bn + __popc(mn & ltmask)] = __expf(vn);
    }
    __syncthreads();

    const int cntP = (int)sCntP;
    const int cntN = (int)sCntN;

    // Contribute local counts to global P,N (each range counted once).
    if (threadIdx.x == 0) {
        if (nj == 0 && cntP) atomicAdd(&g_P, (unsigned)cntP);
        if (pi == 0 && cntN) atomicAdd(&g_N, (unsigned)cntN);
    }

    // ---- pair phase from SMEM ------------------------------------------------
    int G8 = (cntP + 7) >> 3;                 // pos groups of 8
    int nChunk = (cntN + 15) >> 4;            // neg chunks of 16
    const int units = G8 * nChunk;            // ~242 <= TPB typically

    const float4* __restrict__ posf4 = reinterpret_cast<const float4*>(sPos);
    const float4* __restrict__ negf4 = reinterpret_cast<const float4*>(sNeg);
    const u64 S2 = pk2(0.015625f, 0.015625f); // 1/64

    float lgSum = 0.0f;
    int   nUnits = 0;
    for (int u = (int)threadIdx.x; u < units; u += TPB) {
        int chunk = u / G8;                   // consecutive threads share chunk
        int pg    = u - chunk * G8;

        float4 Fa = posf4[2 * pg];
        float4 Fb = posf4[2 * pg + 1];
        u64 Fs0 = mul2(pk2(Fa.x, Fa.y), S2);
        u64 Fs1 = mul2(pk2(Fa.z, Fa.w), S2);
        u64 Fs2 = mul2(pk2(Fb.x, Fb.y), S2);
        u64 Fs3 = mul2(pk2(Fb.z, Fb.w), S2);

        const float4* qp = negf4 + chunk * 4;
        u64 m0 = 0, m1 = 0, m2 = 0, m3 = 0;
#pragma unroll
        for (int k = 0; k < 4; ++k) {
            float4 q = qp[k];
            u64 qx = pk2(q.x, q.x), qy = pk2(q.y, q.y);
            u64 qz = pk2(q.z, q.z), qw = pk2(q.w, q.w);
            u64 p0 = tprod4(qx, qy, qz, qw, Fs0, S2);
            u64 p1 = tprod4(qx, qy, qz, qw, Fs1, S2);
            u64 p2 = tprod4(qx, qy, qz, qw, Fs2, S2);
            u64 p3 = tprod4(qx, qy, qz, qw, Fs3, S2);
            if (k == 0) { m0 = p0; m1 = p1; m2 = p2; m3 = p3; }
            else {
                m0 = mul2(m0, p0); m1 = mul2(m1, p1);
                m2 = mul2(m2, p2); m3 = mul2(m3, p3);
            }
        }
        float a, b;
        upk2(m0, a, b); lgSum += __log2f(a) + __log2f(b);
        upk2(m1, a, b); lgSum += __log2f(a) + __log2f(b);
        upk2(m2, a, b); lgSum += __log2f(a) + __log2f(b);
        upk2(m3, a, b); lgSum += __log2f(a) + __log2f(b);
        ++nUnits;
    }
    // +16*log2(64) = 96 per scalar chain (8 chains/unit); pads cancel exactly.
    float threadSum = (lgSum + 768.0f * (float)nUnits) * 0.6931471805599453f;

    // ---- block reduction ------------------------------------------------------
#pragma unroll
    for (int off = 16; off > 0; off >>= 1)
        threadSum += __shfl_down_sync(0xFFFFFFFFu, threadSum, off);
    if (lane == 0) sRed[warp] = threadSum;
    __syncthreads();
    if (warp == 0) {
        float s = (lane < WARPS) ? sRed[lane] : 0.0f;
#pragma unroll
        for (int off = 16; off > 0; off >>= 1)
            s += __shfl_down_sync(0xFFFFFFFFu, s, off);

        // ---- slotted accumulate + last-block finalize --------------------------
        if (lane == 0) {
            atomicAdd(&g_accSlot[blockIdx.x & (NSLOT - 1)], (double)s);
            __threadfence();
            unsigned int d = atomicAdd(&g_done, 1u);
            if (d == GRID - 1) {
                __threadfence();
                double acc = 0.0;
#pragma unroll
                for (int k = 0; k < NSLOT; ++k) {
                    acc += *(volatile double*)&g_accSlot[k];
                    g_accSlot[k] = 0.0;
                }
                double P = (double)*(volatile unsigned int*)&g_P;
                double N = (double)*(volatile unsigned int*)&g_N;
                out[0] = (float)(acc / (P * N));
                g_P = 0u;
                g_N = 0u;
                g_done = 0u;
            }
        }
    }
}

// ---------------------------------------------------------------------------
extern "C" void kernel_launch(void* const* d_in, const int* in_sizes, int n_in,
                              void* d_out, int out_size) {
    const float* pred  = (const float*)d_in[0];
    const int*   label = (const int*)d_in[1];
    int total = in_sizes[0];   // n*K = 8192

    rul_tile_kernel<<<GRID, TPB>>>(pred, label, total, (float*)d_out);
}